// round 6
// baseline (speedup 1.0000x reference)
#include <cuda_runtime.h>
#include <cstdint>

// ---------------------------------------------------------------------------
// Problem constants
// ---------------------------------------------------------------------------
#define OUT_F 4096
#define IN_F  4096
#define MDIM  16384          // B*S

// GEMM tiling
#define BM 128
#define BN 128
#define BK 16
#define STAGES 4
#define STRIDE 24            // floats per smem row (16 data + 8 pad) — conflict-free LDS.64
#define NKT (IN_F / BK)      // 256 k-tiles

// 320MB module-static scratch (legal: not a runtime allocation)
// Both hold tf32-rounded data in K-PERMUTED layout: within each group of 8 k,
// order is [k0,k4,k1,k5,k2,k6,k3,k7] so fragment pairs (k, k+4) are adjacent.
__device__ float g_Wp[(size_t)OUT_F * IN_F];   // dequantized W [OUT_F][IN_F]
__device__ float g_Ap[(size_t)MDIM * IN_F];    // x [MDIM][IN_F]

__device__ __forceinline__ uint32_t f32_to_tf32(float x) {
    uint32_t u; asm("cvt.rna.tf32.f32 %0, %1;" : "=r"(u) : "f"(x)); return u;
}

// ---------------------------------------------------------------------------
// Prepass 1: dequantize W_q -> g_Wp (tf32-RN, k-permuted).
// W_q flat IS [OUT_F][IN_F] row-major (index algebra: flat = o*4096 + i).
// Param index p = (o&63)*4096 + i. Each thread handles 8 consecutive k.
// ---------------------------------------------------------------------------
__global__ void dequant_kernel(const int* __restrict__ Wq,
                               const float* __restrict__ scale,
                               const float* __restrict__ zero) {
    int f = (blockIdx.x * blockDim.x + threadIdx.x) * 8;
    int o = f >> 12, i = f & 4095;
    int p = ((o & 63) << 12) | i;

    int4   q0 = *reinterpret_cast<const int4*>(Wq + f);
    int4   q1 = *reinterpret_cast<const int4*>(Wq + f + 4);
    float4 z0 = *reinterpret_cast<const float4*>(zero + p);
    float4 z1 = *reinterpret_cast<const float4*>(zero + p + 4);
    float4 s0 = *reinterpret_cast<const float4*>(scale + p);
    float4 s1 = *reinterpret_cast<const float4*>(scale + p + 4);

    uint32_t w0 = f32_to_tf32(((float)q0.x - z0.x) * s0.x);
    uint32_t w1 = f32_to_tf32(((float)q0.y - z0.y) * s0.y);
    uint32_t w2 = f32_to_tf32(((float)q0.z - z0.z) * s0.z);
    uint32_t w3 = f32_to_tf32(((float)q0.w - z0.w) * s0.w);
    uint32_t w4 = f32_to_tf32(((float)q1.x - z1.x) * s1.x);
    uint32_t w5 = f32_to_tf32(((float)q1.y - z1.y) * s1.y);
    uint32_t w6 = f32_to_tf32(((float)q1.z - z1.z) * s1.z);
    uint32_t w7 = f32_to_tf32(((float)q1.w - z1.w) * s1.w);

    // permuted store: [k0,k4,k1,k5] [k2,k6,k3,k7]
    *reinterpret_cast<uint4*>(g_Wp + f)     = make_uint4(w0, w4, w1, w5);
    *reinterpret_cast<uint4*>(g_Wp + f + 4) = make_uint4(w2, w6, w3, w7);
}

// Prepass 2: x -> g_Ap (tf32-RN, k-permuted)
__global__ void round_a_kernel(const float* __restrict__ x) {
    size_t f = (size_t)(blockIdx.x * blockDim.x + threadIdx.x) * 8;
    float4 v0 = *reinterpret_cast<const float4*>(x + f);
    float4 v1 = *reinterpret_cast<const float4*>(x + f + 4);
    uint32_t w0 = f32_to_tf32(v0.x), w1 = f32_to_tf32(v0.y);
    uint32_t w2 = f32_to_tf32(v0.z), w3 = f32_to_tf32(v0.w);
    uint32_t w4 = f32_to_tf32(v1.x), w5 = f32_to_tf32(v1.y);
    uint32_t w6 = f32_to_tf32(v1.z), w7 = f32_to_tf32(v1.w);
    *reinterpret_cast<uint4*>(g_Ap + f)     = make_uint4(w0, w4, w1, w5);
    *reinterpret_cast<uint4*>(g_Ap + f + 4) = make_uint4(w2, w6, w3, w7);
}

// ---------------------------------------------------------------------------
// GEMM: C[m][n] = sum_k A[m][k] * W[n][k] + bias[n]
// 256 threads (8 warps), warp tile 32(m) x 64(n), mma.m16n8k8.tf32,
// 4-stage cp.async pipeline with wait_group 2.
// ---------------------------------------------------------------------------
#define STAGE_FLOATS (BM * STRIDE)    // 3072 floats = 12KB per operand per stage

__global__ void __launch_bounds__(256, 2)
gemm_tf32_kernel(const float* __restrict__ bias, float* __restrict__ C) {
    extern __shared__ float sm[];
    // layout: As[4][128][24] then Bs[4][128][24]
    float* As = sm;
    float* Bs = sm + STAGES * STAGE_FLOATS;

    const float* A = g_Ap;
    const float* B = g_Wp;

    const int tid  = threadIdx.x;
    const int bm   = blockIdx.y * BM;
    const int bn   = blockIdx.x * BN;
    const int warp = tid >> 5;
    const int lane = tid & 31;
    const int wm   = (warp & 3) * 32;
    const int wn   = (warp >> 2) * 64;
    const int grp  = lane >> 2;       // 0..7
    const int tig  = lane & 3;        // 0..3

    float c[2][8][4];
#pragma unroll
    for (int mt = 0; mt < 2; mt++)
#pragma unroll
        for (int nt = 0; nt < 8; nt++)
#pragma unroll
            for (int r = 0; r < 4; r++) c[mt][nt][r] = 0.0f;

    // load mapping: 256 threads, each 2 x 16B per operand per stage
    const int ldrow = tid >> 1;               // 0..127
    const int ldcol = (tid & 1) * 8;          // float offset 0 or 8

#define LOAD_TILE(st, kt)                                                      \
    do {                                                                       \
        const float* ga = A + (size_t)(bm + ldrow) * IN_F + (kt) * BK + ldcol; \
        const float* gb = B + (size_t)(bn + ldrow) * IN_F + (kt) * BK + ldcol; \
        uint32_t sa = (uint32_t)__cvta_generic_to_shared(                      \
            &As[(st) * STAGE_FLOATS + ldrow * STRIDE + ldcol]);                \
        uint32_t sb = (uint32_t)__cvta_generic_to_shared(                      \
            &Bs[(st) * STAGE_FLOATS + ldrow * STRIDE + ldcol]);                \
        asm volatile("cp.async.cg.shared.global [%0], [%1], 16;\n" :: "r"(sa), "l"(ga));       \
        asm volatile("cp.async.cg.shared.global [%0], [%1], 16;\n" :: "r"(sa + 16), "l"(ga + 4)); \
        asm volatile("cp.async.cg.shared.global [%0], [%1], 16;\n" :: "r"(sb), "l"(gb));       \
        asm volatile("cp.async.cg.shared.global [%0], [%1], 16;\n" :: "r"(sb + 16), "l"(gb + 4)); \
    } while (0)

    // prefetch 3 stages
#pragma unroll
    for (int s = 0; s < STAGES - 1; s++) {
        LOAD_TILE(s, s);
        asm volatile("cp.async.commit_group;\n");
    }

#pragma unroll 1
    for (int kt = 0; kt < NKT; kt++) {
        const int st = kt & (STAGES - 1);
        asm volatile("cp.async.wait_group 2;\n");   // group kt complete (3 pending -> 2)
        __syncthreads();

        // issue next tile into stage (kt+3)&3; always commit to keep group count
        if (kt + STAGES - 1 < NKT) LOAD_TILE((kt + STAGES - 1) & (STAGES - 1), kt + STAGES - 1);
        asm volatile("cp.async.commit_group;\n");

        const float* as = &As[st * STAGE_FLOATS];
        const float* bs = &Bs[st * STAGE_FLOATS];

#pragma unroll
        for (int kk = 0; kk < BK; kk += 8) {
            // permuted layout: float2 at (kk + 2*tig) = (k_tig, k_tig+4)
            float2 fa[2][2];   // [mt][row/row+8]
            float2 fb[8];
#pragma unroll
            for (int mt = 0; mt < 2; mt++) {
                int row = wm + mt * 16 + grp;
                fa[mt][0] = *reinterpret_cast<const float2*>(&as[row * STRIDE + kk + 2 * tig]);
                fa[mt][1] = *reinterpret_cast<const float2*>(&as[(row + 8) * STRIDE + kk + 2 * tig]);
            }
#pragma unroll
            for (int nt = 0; nt < 8; nt++) {
                int col = wn + nt * 8 + grp;
                fb[nt] = *reinterpret_cast<const float2*>(&bs[col * STRIDE + kk + 2 * tig]);
            }
#pragma unroll
            for (int mt = 0; mt < 2; mt++)
#pragma unroll
                for (int nt = 0; nt < 8; nt++) {
                    asm volatile(
                        "mma.sync.aligned.m16n8k8.row.col.f32.tf32.tf32.f32 "
                        "{%0,%1,%2,%3}, {%4,%5,%6,%7}, {%8,%9}, {%0,%1,%2,%3};\n"
                        : "+f"(c[mt][nt][0]), "+f"(c[mt][nt][1]),
                          "+f"(c[mt][nt][2]), "+f"(c[mt][nt][3])
                        : "r"(__float_as_uint(fa[mt][0].x)), "r"(__float_as_uint(fa[mt][1].x)),
                          "r"(__float_as_uint(fa[mt][0].y)), "r"(__float_as_uint(fa[mt][1].y)),
                          "r"(__float_as_uint(fb[nt].x)),    "r"(__float_as_uint(fb[nt].y)));
                }
        }
    }

    // Epilogue: bias + float2 stores (cols 2*tig, 2*tig+1 contiguous)
#pragma unroll
    for (int mt = 0; mt < 2; mt++) {
#pragma unroll
        for (int nt = 0; nt < 8; nt++) {
            int row0 = bm + wm + mt * 16 + grp;
            int col  = bn + wn + nt * 8 + tig * 2;
            float b0 = __ldg(bias + col);
            float b1 = __ldg(bias + col + 1);
            float2 v0 = make_float2(c[mt][nt][0] + b0, c[mt][nt][1] + b1);
            float2 v1 = make_float2(c[mt][nt][2] + b0, c[mt][nt][3] + b1);
            *reinterpret_cast<float2*>(C + (size_t)row0 * OUT_F + col) = v0;
            *reinterpret_cast<float2*>(C + (size_t)(row0 + 8) * OUT_F + col) = v1;
        }
    }
}

// ---------------------------------------------------------------------------
// Launch
// ---------------------------------------------------------------------------
extern "C" void kernel_launch(void* const* d_in, const int* in_sizes, int n_in,
                              void* d_out, int out_size) {
    const float* x     = (const float*)d_in[0];  // [16384, 4096] fp32
    const int*   Wq    = (const int*)d_in[1];    // [64, 262144] int32 (u8 values)
    const float* scale = (const float*)d_in[2];  // [1, 262144]
    const float* zero  = (const float*)d_in[3];  // [1, 262144]
    const float* bias  = (const float*)d_in[4];  // [4096]
    float*       out   = (float*)d_out;          // [16384, 4096] fp32

    round_a_kernel<<<(int)((size_t)MDIM * IN_F / 8 / 256), 256>>>(x);
    dequant_kernel<<<(OUT_F * IN_F) / 8 / 256, 256>>>(Wq, scale, zero);

    const int smem_bytes = 2 * STAGES * STAGE_FLOATS * sizeof(float);  // 96KB
    static int configured = 0;
    cudaFuncSetAttribute(gemm_tf32_kernel,
                         cudaFuncAttributeMaxDynamicSharedMemorySize, smem_bytes);
    (void)configured;

    dim3 grid(OUT_F / BN, MDIM / BM);   // (32, 128)
    gemm_tf32_kernel<<<grid, 256, smem_bytes>>>(bias, out);
}